// round 14
// baseline (speedup 1.0000x reference)
#include <cuda_runtime.h>

#define NSTEP 8192
#define NUDIM 4
#define RB    128
#define NXDIM 64
#define NYDIM 4
#define LBLK  32
#define MBLK  (NSTEP / LBLK)

__device__ float g_F [MBLK * RB * NXDIM];
__device__ float g_Xs[MBLK * RB * NXDIM];
__device__ float g_A32[NXDIM * NXDIM];
__device__ float g_G [NXDIM * (LBLK * NUDIM)];
__device__ int   g_flag[MBLK];

typedef unsigned long long ull;
#define FFMA2(d, a, b)  asm("fma.rn.f32x2 %0, %1, %2, %0;" : "+l"(d) : "l"(a), "l"(b))
#define PACKB(d, s)     asm("mov.b64 %0, {%1, %1};" : "=l"(d) : "f"(s))
#define PACK2(d, lo, hi) asm("mov.b64 %0, {%1, %2};" : "=l"(d) : "f"(lo), "f"(hi))
#define UNPACK2(lo, hi, p) asm("mov.b64 {%0, %1}, %2;" : "=f"(lo), "=f"(hi) : "l"(p))

__device__ __forceinline__ int swz(int row, int r) { return r ^ (((row >> 2) & 7) << 2); }

// ---------------- Kernel 1: A^32 + G by doubling (+ flag reset) ----------------
__global__ void k_powers(const float* __restrict__ A, const float* __restrict__ Bu) {
    extern __shared__ float ps[];
    float* Asm = ps;                 // 64 x 65
    float* P   = ps + NXDIM * 65;    // 64 x 128
    int t = threadIdx.x;
    g_flag[t] = 0;                   // reset handshake flags (MBLK == 256)
    for (int idx = t; idx < NXDIM * NXDIM; idx += 256)
        Asm[(idx / NXDIM) * 65 + (idx % NXDIM)] = A[idx];
    P[(t >> 2) * 128 + (t & 3)] = Bu[t];
    __syncthreads();
    int W = 4;
    int oi = t >> 2, oj0 = (t & 3) * 16;
    for (int s = 0; s < 5; s++) {
        for (int idx = t; idx < NXDIM * W; idx += 256) {
            int i = idx / W, k = idx % W;
            float s0 = 0.f, s1 = 0.f, s2 = 0.f, s3 = 0.f;
            #pragma unroll 4
            for (int j = 0; j < NXDIM; j += 4) {
                s0 += Asm[i * 65 + j]     * P[(j)     * 128 + k];
                s1 += Asm[i * 65 + j + 1] * P[(j + 1) * 128 + k];
                s2 += Asm[i * 65 + j + 2] * P[(j + 2) * 128 + k];
                s3 += Asm[i * 65 + j + 3] * P[(j + 3) * 128 + k];
            }
            P[i * 128 + W + k] = (s0 + s1) + (s2 + s3);
        }
        __syncthreads();
        float accq[16];
        #pragma unroll
        for (int jj = 0; jj < 16; jj++) accq[jj] = 0.f;
        for (int k = 0; k < NXDIM; k++) {
            float a = Asm[oi * 65 + k];
            #pragma unroll
            for (int jj = 0; jj < 16; jj++) accq[jj] += a * Asm[k * 65 + oj0 + jj];
        }
        __syncthreads();
        #pragma unroll
        for (int jj = 0; jj < 16; jj++) Asm[oi * 65 + oj0 + jj] = accq[jj];
        __syncthreads();
        W <<= 1;
    }
    for (int idx = t; idx < NXDIM * NXDIM; idx += 256)
        g_A32[idx] = Asm[(idx / NXDIM) * 65 + (idx % NXDIM)];
    for (int idx = t; idx < NXDIM * 128; idx += 256) {
        int i = idx >> 7, col = idx & 127;
        int m = col >> 2, q = col & 3;
        g_G[i * 128 + ((31 - m) << 2) + q] = P[idx];
    }
}

// ---------------- Fused kernel: fgemm (CTAs 0..255) + scan (CTAs 256..383) ----------------
// fgemm CTA c publishes g_flag[c] after writing F[c]; scan CTAs spin-wait
// before each F prefetch. Scan overlaps fgemm almost entirely.
__global__ void __launch_bounds__(256) k_fscan(const float* __restrict__ u) {
    extern __shared__ float sm[];
    int t = threadIdx.x;

    if (blockIdx.x < MBLK) {
        // ================= fgemm part (R8 body) =================
        float* Gt = sm;
        float* Ut = sm + 128 * NXDIM;
        int c = blockIdx.x;
        int rb = t & 15, ib = t >> 4;
        int r0 = rb * 8, i0 = ib * 4;
        for (int idx = t; idx < 128 * NXDIM; idx += 256) {
            int i = idx >> 7, k = idx & 127;
            Gt[k * NXDIM + i] = g_G[idx];
        }
        ull pacc[4][4];
        #pragma unroll
        for (int ii = 0; ii < 4; ii++)
            #pragma unroll
            for (int rp = 0; rp < 4; rp++) pacc[ii][rp] = 0ull;
        const float* ublk = u + (size_t)c * (LBLK * NUDIM * RB);
        for (int k0 = 0; k0 < 128; k0 += 32) {
            __syncthreads();
            for (int idx = t; idx < 32 * 128; idx += 256)
                Ut[idx] = ublk[(k0 + (idx >> 7)) * 128 + (idx & 127)];
            __syncthreads();
            #pragma unroll 8
            for (int kk = 0; kk < 32; kk++) {
                float4 g = *(const float4*)(Gt + (k0 + kk) * NXDIM + i0);
                ull g0, g1, g2, g3;
                PACKB(g0, g.x); PACKB(g1, g.y); PACKB(g2, g.z); PACKB(g3, g.w);
                ulonglong2 ua = *(const ulonglong2*)(Ut + kk * 128 + r0);
                ulonglong2 ub = *(const ulonglong2*)(Ut + kk * 128 + r0 + 4);
                ull s0 = ua.x, s1 = ua.y, s2 = ub.x, s3 = ub.y;
                FFMA2(pacc[0][0], g0, s0); FFMA2(pacc[1][0], g1, s0); FFMA2(pacc[2][0], g2, s0); FFMA2(pacc[3][0], g3, s0);
                FFMA2(pacc[0][1], g0, s1); FFMA2(pacc[1][1], g1, s1); FFMA2(pacc[2][1], g2, s1); FFMA2(pacc[3][1], g3, s1);
                FFMA2(pacc[0][2], g0, s2); FFMA2(pacc[1][2], g1, s2); FFMA2(pacc[2][2], g2, s2); FFMA2(pacc[3][2], g3, s2);
                FFMA2(pacc[0][3], g0, s3); FFMA2(pacc[1][3], g1, s3); FFMA2(pacc[2][3], g2, s3); FFMA2(pacc[3][3], g3, s3);
            }
        }
        float v[4][8];
        #pragma unroll
        for (int ii = 0; ii < 4; ii++)
            #pragma unroll
            for (int rp = 0; rp < 4; rp++)
                UNPACK2(v[ii][2 * rp], v[ii][2 * rp + 1], pacc[ii][rp]);
        float* f = g_F + (size_t)c * (RB * NXDIM);
        #pragma unroll
        for (int rr = 0; rr < 8; rr++)
            *(float4*)(f + (r0 + rr) * NXDIM + i0) =
                make_float4(v[0][rr], v[1][rr], v[2][rr], v[3][rr]);
        // publish
        __threadfence();
        __syncthreads();
        if (t == 0) atomicExch(&g_flag[c], 1);
    } else {
        // ================= scan part (R8 body + flag waits) =================
        float* xsh0 = sm;            // 2 x 64 floats
        float* xsh1 = sm + NXDIM;
        int r = blockIdx.x - MBLK;
        int i = t >> 1, h = t & 1;
        const int PF = 4;

        float arow[32];
        float fbuf[PF];
        float x = 0.f;

        if (t < 128) {
            #pragma unroll
            for (int jj = 0; jj < 32; jj += 4) {
                float4 vv = *(const float4*)(g_A32 + i * NXDIM + h * 32 + jj);
                arow[jj] = vv.x; arow[jj + 1] = vv.y; arow[jj + 2] = vv.z; arow[jj + 3] = vv.w;
            }
            #pragma unroll
            for (int p = 0; p < PF; p++) {
                while (((volatile int*)g_flag)[p] == 0) __nanosleep(128);
                __threadfence();
                fbuf[p] = g_F[((size_t)p * RB + r) * NXDIM + i];
            }
            if (t < NXDIM) xsh0[t] = 0.f;
        }
        __syncthreads();
        int cur = 0;
        for (int c = 0; c < MBLK; c++) {
            if (t < 128) {
                float* xc = cur ? xsh1 : xsh0;
                float* xn = cur ? xsh0 : xsh1;
                if (h) g_Xs[((size_t)c * RB + r) * NXDIM + i] = x;
                float fv = fbuf[c & (PF - 1)];
                if (c + PF < MBLK) {
                    while (((volatile int*)g_flag)[c + PF] == 0) __nanosleep(128);
                    __threadfence();
                    fbuf[c & (PF - 1)] = g_F[((size_t)(c + PF) * RB + r) * NXDIM + i];
                }
                float v0 = 0.f, v1 = 0.f, v2 = 0.f, v3 = 0.f;
                const float* xh = xc + h * 32;
                #pragma unroll
                for (int jj = 0; jj < 32; jj += 4) {
                    float4 xv = *(const float4*)(xh + jj);
                    v0 += arow[jj]     * xv.x;
                    v1 += arow[jj + 1] * xv.y;
                    v2 += arow[jj + 2] * xv.z;
                    v3 += arow[jj + 3] * xv.w;
                }
                float part = (v0 + v1) + (v2 + v3);
                part += __shfl_xor_sync(0xffffffffu, part, 1);
                x = part + fv;
                if (!h) xn[i] = x;
            }
            __syncthreads();
            cur ^= 1;
        }
    }
}

// ---------------- Kernel 4: expansion (R8 verbatim) ----------------
#define SSLOT (NXDIM * RB)
#define USLOT (NUDIM * RB)
__global__ void __launch_bounds__(256, 2) k_expand(
    const float* __restrict__ u, const float* __restrict__ A,
    const float* __restrict__ Bu, const float* __restrict__ Cy,
    const float* __restrict__ Dyu,
    float* __restrict__ outY, float* __restrict__ outX) {
    extern __shared__ float sm[];
    float* At  = sm;
    float* Bt  = At + NXDIM * NXDIM;
    float* CsT = Bt + NUDIM * NXDIM;
    float* ssh = CsT + NXDIM * NYDIM;        // 2 x 8192
    float* ush = ssh + 2 * SSLOT;            // 2 x 512

    int t = threadIdx.x, c = blockIdx.x;
    int w = t >> 5, l = t & 31;
    int iW = (w & 1) << 5, rW = (w >> 1) << 5;
    int i0 = iW + ((l & 7) << 2);
    int r0 = rW + ((l >> 3) << 3);

    for (int idx = t; idx < NXDIM * NXDIM; idx += 256)
        At[(idx % NXDIM) * NXDIM + (idx / NXDIM)] = A[idx];
    if (t < NUDIM * NXDIM) Bt[(t & 3) * NXDIM + (t >> 2)] = Bu[t];
    if (t < NXDIM * NYDIM) CsT[t] = Cy[(t & 3) * NXDIM + (t >> 2)];

    float d00 = Dyu[0],  d01 = Dyu[1],  d02 = Dyu[2],  d03 = Dyu[3];
    float d10 = Dyu[4],  d11 = Dyu[5],  d12 = Dyu[6],  d13 = Dyu[7];
    float d20 = Dyu[8],  d21 = Dyu[9],  d22 = Dyu[10], d23 = Dyu[11];
    float d30 = Dyu[12], d31 = Dyu[13], d32 = Dyu[14], d33 = Dyu[15];

    ull pacc[4][4];
    {
        const float* xs = g_Xs + (size_t)c * (RB * NXDIM);
        float vv[8][4];
        #pragma unroll
        for (int rr = 0; rr < 8; rr++) {
            float4 v = *(const float4*)(xs + (r0 + rr) * NXDIM + i0);
            vv[rr][0] = v.x; vv[rr][1] = v.y; vv[rr][2] = v.z; vv[rr][3] = v.w;
        }
        #pragma unroll
        for (int ii = 0; ii < 4; ii++)
            #pragma unroll
            for (int rp = 0; rp < 4; rp++)
                PACK2(pacc[ii][rp], vv[2 * rp][ii], vv[2 * rp + 1][ii]);
    }
    #pragma unroll
    for (int ii = 0; ii < 4; ii++) {
        int i = i0 + ii;
        int rs = swz(i, r0);
        *(ulonglong2*)(ssh + i * RB + rs)       = make_ulonglong2(pacc[ii][0], pacc[ii][1]);
        *(ulonglong2*)(ssh + i * RB + (rs ^ 4)) = make_ulonglong2(pacc[ii][2], pacc[ii][3]);
    }

    const float* ub = u + (size_t)c * LBLK * (NUDIM * RB);
    ((float2*)ush)[t] = *(const float2*)(ub + t * 2);
    float2 upf = *(const float2*)(ub + 1 * (NUDIM * RB) + t * 2);
    int yr = t & 127;
    __syncthreads();

    for (int d = 0; d < LBLK; d++) {
        float* sshC = ssh + (d & 1) * SSLOT;
        float* sshN = ssh + ((d & 1) ^ 1) * SSLOT;
        float* ushC = ush + (d & 1) * USLOT;
        float* ushN = ush + ((d & 1) ^ 1) * USLOT;

        if (d + 1 < LBLK) {
            ((float2*)ushN)[t] = upf;
            if (d + 2 < LBLK)
                upf = *(const float2*)(ub + (d + 2) * (NUDIM * RB) + t * 2);
        }

        size_t k = (size_t)c * LBLK + d;

        float* xo = outX + k * (NXDIM * RB);
        #pragma unroll
        for (int ii = 0; ii < 4; ii++) {
            *(ulonglong2*)(xo + (size_t)(i0 + ii) * RB + r0)     = make_ulonglong2(pacc[ii][0], pacc[ii][1]);
            *(ulonglong2*)(xo + (size_t)(i0 + ii) * RB + r0 + 4) = make_ulonglong2(pacc[ii][2], pacc[ii][3]);
        }

        if (t < 128) {
            float u0 = ushC[yr], u1 = ushC[RB + yr], u2 = ushC[2 * RB + yr], u3 = ushC[3 * RB + yr];
            float y0 = d00 * u0 + d01 * u1 + d02 * u2 + d03 * u3;
            float y1 = d10 * u0 + d11 * u1 + d12 * u2 + d13 * u3;
            float y2 = d20 * u0 + d21 * u1 + d22 * u2 + d23 * u3;
            float y3 = d30 * u0 + d31 * u1 + d32 * u2 + d33 * u3;
            #pragma unroll 8
            for (int j = 0; j < NXDIM; j++) {
                float s = sshC[j * RB + (yr ^ (((j >> 2) & 7) << 2))];
                float4 cv = *(const float4*)(CsT + j * 4);
                y0 += cv.x * s; y1 += cv.y * s; y2 += cv.z * s; y3 += cv.w * s;
            }
            float* yo = outY + k * (NYDIM * RB);
            yo[yr] = y0; yo[RB + yr] = y1; yo[2 * RB + yr] = y2; yo[3 * RB + yr] = y3;
        }

        #pragma unroll
        for (int ii = 0; ii < 4; ii++)
            #pragma unroll
            for (int rp = 0; rp < 4; rp++) pacc[ii][rp] = 0ull;

        #pragma unroll
        for (int q = 0; q < NUDIM; q++) {
            float4 b = *(const float4*)(Bt + q * NXDIM + i0);
            ull b0, b1, b2, b3;
            PACKB(b0, b.x); PACKB(b1, b.y); PACKB(b2, b.z); PACKB(b3, b.w);
            ulonglong2 ua = *(const ulonglong2*)(ushC + q * RB + r0);
            ulonglong2 ubp = *(const ulonglong2*)(ushC + q * RB + r0 + 4);
            ull s0 = ua.x, s1 = ua.y, s2 = ubp.x, s3 = ubp.y;
            FFMA2(pacc[0][0], b0, s0); FFMA2(pacc[1][0], b1, s0); FFMA2(pacc[2][0], b2, s0); FFMA2(pacc[3][0], b3, s0);
            FFMA2(pacc[0][1], b0, s1); FFMA2(pacc[1][1], b1, s1); FFMA2(pacc[2][1], b2, s1); FFMA2(pacc[3][1], b3, s1);
            FFMA2(pacc[0][2], b0, s2); FFMA2(pacc[1][2], b1, s2); FFMA2(pacc[2][2], b2, s2); FFMA2(pacc[3][2], b3, s2);
            FFMA2(pacc[0][3], b0, s3); FFMA2(pacc[1][3], b1, s3); FFMA2(pacc[2][3], b2, s3); FFMA2(pacc[3][3], b3, s3);
        }
        #pragma unroll 8
        for (int j = 0; j < NXDIM; j++) {
            float4 a = *(const float4*)(At + j * NXDIM + i0);
            ull a0, a1, a2, a3;
            PACKB(a0, a.x); PACKB(a1, a.y); PACKB(a2, a.z); PACKB(a3, a.w);
            int rs = j * RB + swz(j, r0);
            ulonglong2 sa = *(const ulonglong2*)(sshC + rs);
            ulonglong2 sb = *(const ulonglong2*)(sshC + (rs ^ 4));
            ull s0 = sa.x, s1 = sa.y, s2 = sb.x, s3 = sb.y;
            FFMA2(pacc[0][0], a0, s0); FFMA2(pacc[1][0], a1, s0); FFMA2(pacc[2][0], a2, s0); FFMA2(pacc[3][0], a3, s0);
            FFMA2(pacc[0][1], a0, s1); FFMA2(pacc[1][1], a1, s1); FFMA2(pacc[2][1], a2, s1); FFMA2(pacc[3][1], a3, s1);
            FFMA2(pacc[0][2], a0, s2); FFMA2(pacc[1][2], a1, s2); FFMA2(pacc[2][2], a2, s2); FFMA2(pacc[3][2], a3, s2);
            FFMA2(pacc[0][3], a0, s3); FFMA2(pacc[1][3], a1, s3); FFMA2(pacc[2][3], a2, s3); FFMA2(pacc[3][3], a3, s3);
        }

        #pragma unroll
        for (int ii = 0; ii < 4; ii++) {
            int i = i0 + ii;
            int rs = swz(i, r0);
            *(ulonglong2*)(sshN + i * RB + rs)       = make_ulonglong2(pacc[ii][0], pacc[ii][1]);
            *(ulonglong2*)(sshN + i * RB + (rs ^ 4)) = make_ulonglong2(pacc[ii][2], pacc[ii][3]);
        }
        __syncthreads();
    }
}

// ---------------------------------------------------------------------------
extern "C" void kernel_launch(void* const* d_in, const int* in_sizes, int n_in,
                              void* d_out, int out_size) {
    (void)in_sizes; (void)n_in; (void)out_size;
    const float* u   = (const float*)d_in[0];
    const float* A   = (const float*)d_in[1];
    const float* Bu  = (const float*)d_in[2];
    const float* Cy  = (const float*)d_in[3];
    const float* Dyu = (const float*)d_in[4];
    float* outY = (float*)d_out;
    float* outX = outY + (size_t)NSTEP * NYDIM * RB;

    const int smem_powers = (NXDIM * 65 + NXDIM * 128) * (int)sizeof(float);
    const int smem_fscan  = (128 * NXDIM + 32 * 128) * (int)sizeof(float);   // 48 KB (fgemm part)
    const int smem_expand = (NXDIM * NXDIM + NUDIM * NXDIM + NXDIM * NYDIM +
                             2 * SSLOT + 2 * USLOT) * (int)sizeof(float);    // ~88 KB

    cudaFuncSetAttribute(k_powers, cudaFuncAttributeMaxDynamicSharedMemorySize, smem_powers);
    cudaFuncSetAttribute(k_fscan,  cudaFuncAttributeMaxDynamicSharedMemorySize, smem_fscan);
    cudaFuncSetAttribute(k_expand, cudaFuncAttributeMaxDynamicSharedMemorySize, smem_expand);

    k_powers<<<1, 256, smem_powers>>>(A, Bu);
    k_fscan<<<MBLK + RB, 256, smem_fscan>>>(u);
    k_expand<<<MBLK, 256, smem_expand>>>(u, A, Bu, Cy, Dyu, outY, outX);
}

// round 15
// speedup vs baseline: 1.4999x; 1.4999x over previous
#include <cuda_runtime.h>

#define NSTEP 8192
#define NUDIM 4
#define RB    128
#define NXDIM 64
#define NYDIM 4
#define LBLK  32
#define MBLK  (NSTEP / LBLK)

__device__ float g_F [MBLK * RB * NXDIM];
__device__ float g_Xs[MBLK * RB * NXDIM];
__device__ float g_A32[NXDIM * NXDIM];
__device__ float g_G [NXDIM * (LBLK * NUDIM)];

typedef unsigned long long ull;
#define FFMA2(d, a, b)  asm("fma.rn.f32x2 %0, %1, %2, %0;" : "+l"(d) : "l"(a), "l"(b))
#define PACKB(d, s)     asm("mov.b64 %0, {%1, %1};" : "=l"(d) : "f"(s))
#define PACK2(d, lo, hi) asm("mov.b64 %0, {%1, %2};" : "=l"(d) : "f"(lo), "f"(hi))
#define UNPACK2(lo, hi, p) asm("mov.b64 {%0, %1}, %2;" : "=f"(lo), "=f"(hi) : "l"(p))

__device__ __forceinline__ int swz(int row, int r) { return r ^ (((row >> 2) & 7) << 2); }

// ---------------- Kernel 1: A^32 + G by doubling, 1024 threads ----------------
// Squarings: 4 outputs/thread (vs 16) at 32 warps -> 4x shorter latency chain.
__global__ void __launch_bounds__(1024) k_powers(const float* __restrict__ A, const float* __restrict__ Bu) {
    extern __shared__ float ps[];
    float* Asm = ps;                 // 64 x 65
    float* P   = ps + NXDIM * 65;    // 64 x 128
    int t = threadIdx.x;             // 1024

    for (int idx = t; idx < NXDIM * NXDIM; idx += 1024)
        Asm[(idx >> 6) * 65 + (idx & 63)] = A[idx];
    if (t < 256) P[(t >> 2) * 128 + (t & 3)] = Bu[t];
    __syncthreads();

    int W = 4;
    int oi = t >> 4, oj0 = (t & 15) * 4;     // 64 rows x 16 col-groups of 4
    for (int s = 0; s < 5; s++) {
        // append: P[:, W+k] = Asm @ P[:, k]  (k < W)
        for (int idx = t; idx < NXDIM * W; idx += 1024) {
            int i = idx / W, k = idx % W;
            float s0 = 0.f, s1 = 0.f, s2 = 0.f, s3 = 0.f;
            #pragma unroll 4
            for (int j = 0; j < NXDIM; j += 4) {
                s0 += Asm[i * 65 + j]     * P[(j)     * 128 + k];
                s1 += Asm[i * 65 + j + 1] * P[(j + 1) * 128 + k];
                s2 += Asm[i * 65 + j + 2] * P[(j + 2) * 128 + k];
                s3 += Asm[i * 65 + j + 3] * P[(j + 3) * 128 + k];
            }
            P[i * 128 + W + k] = (s0 + s1) + (s2 + s3);
        }
        __syncthreads();
        // square Asm: 4 outputs per thread
        float a0 = 0.f, a1 = 0.f, a2 = 0.f, a3 = 0.f;
        #pragma unroll 8
        for (int k = 0; k < NXDIM; k++) {
            float a = Asm[oi * 65 + k];
            const float* row = Asm + k * 65 + oj0;
            a0 += a * row[0]; a1 += a * row[1]; a2 += a * row[2]; a3 += a * row[3];
        }
        __syncthreads();
        Asm[oi * 65 + oj0]     = a0;
        Asm[oi * 65 + oj0 + 1] = a1;
        Asm[oi * 65 + oj0 + 2] = a2;
        Asm[oi * 65 + oj0 + 3] = a3;
        __syncthreads();
        W <<= 1;
    }

    for (int idx = t; idx < NXDIM * NXDIM; idx += 1024)
        g_A32[idx] = Asm[(idx >> 6) * 65 + (idx & 63)];
    for (int idx = t; idx < NXDIM * 128; idx += 1024) {
        int i = idx >> 7, col = idx & 127;
        int m = col >> 2, q = col & 3;
        g_G[i * 128 + ((31 - m) << 2) + q] = P[idx];
    }
}

// ---------------- Kernel 2: f_c = G @ U_c (FFMA2, R8 verbatim) ----------------
__global__ void __launch_bounds__(256) k_fgemm(const float* __restrict__ u) {
    extern __shared__ float sm[];
    float* Gt = sm;
    float* Ut = sm + 128 * NXDIM;
    int t = threadIdx.x, c = blockIdx.x;
    int rb = t & 15, ib = t >> 4;
    int r0 = rb * 8, i0 = ib * 4;
    for (int idx = t; idx < 128 * NXDIM; idx += 256) {
        int i = idx >> 7, k = idx & 127;
        Gt[k * NXDIM + i] = g_G[idx];
    }
    ull pacc[4][4];
    #pragma unroll
    for (int ii = 0; ii < 4; ii++)
        #pragma unroll
        for (int rp = 0; rp < 4; rp++) pacc[ii][rp] = 0ull;
    const float* ublk = u + (size_t)c * (LBLK * NUDIM * RB);
    for (int k0 = 0; k0 < 128; k0 += 32) {
        __syncthreads();
        for (int idx = t; idx < 32 * 128; idx += 256)
            Ut[idx] = ublk[(k0 + (idx >> 7)) * 128 + (idx & 127)];
        __syncthreads();
        #pragma unroll 8
        for (int kk = 0; kk < 32; kk++) {
            float4 g = *(const float4*)(Gt + (k0 + kk) * NXDIM + i0);
            ull g0, g1, g2, g3;
            PACKB(g0, g.x); PACKB(g1, g.y); PACKB(g2, g.z); PACKB(g3, g.w);
            ulonglong2 ua = *(const ulonglong2*)(Ut + kk * 128 + r0);
            ulonglong2 ub = *(const ulonglong2*)(Ut + kk * 128 + r0 + 4);
            ull s0 = ua.x, s1 = ua.y, s2 = ub.x, s3 = ub.y;
            FFMA2(pacc[0][0], g0, s0); FFMA2(pacc[1][0], g1, s0); FFMA2(pacc[2][0], g2, s0); FFMA2(pacc[3][0], g3, s0);
            FFMA2(pacc[0][1], g0, s1); FFMA2(pacc[1][1], g1, s1); FFMA2(pacc[2][1], g2, s1); FFMA2(pacc[3][1], g3, s1);
            FFMA2(pacc[0][2], g0, s2); FFMA2(pacc[1][2], g1, s2); FFMA2(pacc[2][2], g2, s2); FFMA2(pacc[3][2], g3, s2);
            FFMA2(pacc[0][3], g0, s3); FFMA2(pacc[1][3], g1, s3); FFMA2(pacc[2][3], g2, s3); FFMA2(pacc[3][3], g3, s3);
        }
    }
    float v[4][8];
    #pragma unroll
    for (int ii = 0; ii < 4; ii++)
        #pragma unroll
        for (int rp = 0; rp < 4; rp++)
            UNPACK2(v[ii][2 * rp], v[ii][2 * rp + 1], pacc[ii][rp]);
    float* f = g_F + (size_t)c * (RB * NXDIM);
    #pragma unroll
    for (int rr = 0; rr < 8; rr++)
        *(float4*)(f + (r0 + rr) * NXDIM + i0) =
            make_float4(v[0][rr], v[1][rr], v[2][rr], v[3][rr]);
}

// ---------------- Kernel 3: block scan (R8 verbatim) ----------------
__global__ void __launch_bounds__(128) k_scan() {
    __shared__ float xsh[2][NXDIM];
    int r = blockIdx.x;
    int t = threadIdx.x;
    int i = t >> 1, h = t & 1;
    float arow[32];
    #pragma unroll
    for (int jj = 0; jj < 32; jj += 4) {
        float4 v = *(const float4*)(g_A32 + i * NXDIM + h * 32 + jj);
        arow[jj] = v.x; arow[jj + 1] = v.y; arow[jj + 2] = v.z; arow[jj + 3] = v.w;
    }
    const int PF = 4;
    float fbuf[PF];
    #pragma unroll
    for (int p = 0; p < PF; p++)
        fbuf[p] = g_F[((size_t)p * RB + r) * NXDIM + i];
    float x = 0.f;
    if (t < NXDIM) xsh[0][t] = 0.f;
    __syncthreads();
    int cur = 0;
    for (int c = 0; c < MBLK; c++) {
        if (h) g_Xs[((size_t)c * RB + r) * NXDIM + i] = x;
        float fv = fbuf[c & (PF - 1)];
        if (c + PF < MBLK)
            fbuf[c & (PF - 1)] = g_F[((size_t)(c + PF) * RB + r) * NXDIM + i];
        float v0 = 0.f, v1 = 0.f, v2 = 0.f, v3 = 0.f;
        const float* xh = &xsh[cur][h * 32];
        #pragma unroll
        for (int jj = 0; jj < 32; jj += 4) {
            float4 xv = *(const float4*)(xh + jj);
            v0 += arow[jj]     * xv.x;
            v1 += arow[jj + 1] * xv.y;
            v2 += arow[jj + 2] * xv.z;
            v3 += arow[jj + 3] * xv.w;
        }
        float part = (v0 + v1) + (v2 + v3);
        part += __shfl_xor_sync(0xffffffffu, part, 1);
        x = part + fv;
        if (!h) xsh[cur ^ 1][i] = x;
        __syncthreads();
        cur ^= 1;
    }
}

// ---------------- Kernel 4: expansion (R8 verbatim) ----------------
#define SSLOT (NXDIM * RB)
#define USLOT (NUDIM * RB)
__global__ void __launch_bounds__(256, 2) k_expand(
    const float* __restrict__ u, const float* __restrict__ A,
    const float* __restrict__ Bu, const float* __restrict__ Cy,
    const float* __restrict__ Dyu,
    float* __restrict__ outY, float* __restrict__ outX) {
    extern __shared__ float sm[];
    float* At  = sm;
    float* Bt  = At + NXDIM * NXDIM;
    float* CsT = Bt + NUDIM * NXDIM;
    float* ssh = CsT + NXDIM * NYDIM;        // 2 x 8192
    float* ush = ssh + 2 * SSLOT;            // 2 x 512

    int t = threadIdx.x, c = blockIdx.x;
    int w = t >> 5, l = t & 31;
    int iW = (w & 1) << 5, rW = (w >> 1) << 5;
    int i0 = iW + ((l & 7) << 2);
    int r0 = rW + ((l >> 3) << 3);

    for (int idx = t; idx < NXDIM * NXDIM; idx += 256)
        At[(idx % NXDIM) * NXDIM + (idx / NXDIM)] = A[idx];
    if (t < NUDIM * NXDIM) Bt[(t & 3) * NXDIM + (t >> 2)] = Bu[t];
    if (t < NXDIM * NYDIM) CsT[t] = Cy[(t & 3) * NXDIM + (t >> 2)];

    float d00 = Dyu[0],  d01 = Dyu[1],  d02 = Dyu[2],  d03 = Dyu[3];
    float d10 = Dyu[4],  d11 = Dyu[5],  d12 = Dyu[6],  d13 = Dyu[7];
    float d20 = Dyu[8],  d21 = Dyu[9],  d22 = Dyu[10], d23 = Dyu[11];
    float d30 = Dyu[12], d31 = Dyu[13], d32 = Dyu[14], d33 = Dyu[15];

    ull pacc[4][4];
    {
        const float* xs = g_Xs + (size_t)c * (RB * NXDIM);
        float vv[8][4];
        #pragma unroll
        for (int rr = 0; rr < 8; rr++) {
            float4 v = *(const float4*)(xs + (r0 + rr) * NXDIM + i0);
            vv[rr][0] = v.x; vv[rr][1] = v.y; vv[rr][2] = v.z; vv[rr][3] = v.w;
        }
        #pragma unroll
        for (int ii = 0; ii < 4; ii++)
            #pragma unroll
            for (int rp = 0; rp < 4; rp++)
                PACK2(pacc[ii][rp], vv[2 * rp][ii], vv[2 * rp + 1][ii]);
    }
    #pragma unroll
    for (int ii = 0; ii < 4; ii++) {
        int i = i0 + ii;
        int rs = swz(i, r0);
        *(ulonglong2*)(ssh + i * RB + rs)       = make_ulonglong2(pacc[ii][0], pacc[ii][1]);
        *(ulonglong2*)(ssh + i * RB + (rs ^ 4)) = make_ulonglong2(pacc[ii][2], pacc[ii][3]);
    }

    const float* ub = u + (size_t)c * LBLK * (NUDIM * RB);
    ((float2*)ush)[t] = *(const float2*)(ub + t * 2);
    float2 upf = *(const float2*)(ub + 1 * (NUDIM * RB) + t * 2);
    int yr = t & 127;
    __syncthreads();

    for (int d = 0; d < LBLK; d++) {
        float* sshC = ssh + (d & 1) * SSLOT;
        float* sshN = ssh + ((d & 1) ^ 1) * SSLOT;
        float* ushC = ush + (d & 1) * USLOT;
        float* ushN = ush + ((d & 1) ^ 1) * USLOT;

        if (d + 1 < LBLK) {
            ((float2*)ushN)[t] = upf;
            if (d + 2 < LBLK)
                upf = *(const float2*)(ub + (d + 2) * (NUDIM * RB) + t * 2);
        }

        size_t k = (size_t)c * LBLK + d;

        float* xo = outX + k * (NXDIM * RB);
        #pragma unroll
        for (int ii = 0; ii < 4; ii++) {
            *(ulonglong2*)(xo + (size_t)(i0 + ii) * RB + r0)     = make_ulonglong2(pacc[ii][0], pacc[ii][1]);
            *(ulonglong2*)(xo + (size_t)(i0 + ii) * RB + r0 + 4) = make_ulonglong2(pacc[ii][2], pacc[ii][3]);
        }

        if (t < 128) {
            float u0 = ushC[yr], u1 = ushC[RB + yr], u2 = ushC[2 * RB + yr], u3 = ushC[3 * RB + yr];
            float y0 = d00 * u0 + d01 * u1 + d02 * u2 + d03 * u3;
            float y1 = d10 * u0 + d11 * u1 + d12 * u2 + d13 * u3;
            float y2 = d20 * u0 + d21 * u1 + d22 * u2 + d23 * u3;
            float y3 = d30 * u0 + d31 * u1 + d32 * u2 + d33 * u3;
            #pragma unroll 8
            for (int j = 0; j < NXDIM; j++) {
                float s = sshC[j * RB + (yr ^ (((j >> 2) & 7) << 2))];
                float4 cv = *(const float4*)(CsT + j * 4);
                y0 += cv.x * s; y1 += cv.y * s; y2 += cv.z * s; y3 += cv.w * s;
            }
            float* yo = outY + k * (NYDIM * RB);
            yo[yr] = y0; yo[RB + yr] = y1; yo[2 * RB + yr] = y2; yo[3 * RB + yr] = y3;
        }

        #pragma unroll
        for (int ii = 0; ii < 4; ii++)
            #pragma unroll
            for (int rp = 0; rp < 4; rp++) pacc[ii][rp] = 0ull;

        #pragma unroll
        for (int q = 0; q < NUDIM; q++) {
            float4 b = *(const float4*)(Bt + q * NXDIM + i0);
            ull b0, b1, b2, b3;
            PACKB(b0, b.x); PACKB(b1, b.y); PACKB(b2, b.z); PACKB(b3, b.w);
            ulonglong2 ua = *(const ulonglong2*)(ushC + q * RB + r0);
            ulonglong2 ubp = *(const ulonglong2*)(ushC + q * RB + r0 + 4);
            ull s0 = ua.x, s1 = ua.y, s2 = ubp.x, s3 = ubp.y;
            FFMA2(pacc[0][0], b0, s0); FFMA2(pacc[1][0], b1, s0); FFMA2(pacc[2][0], b2, s0); FFMA2(pacc[3][0], b3, s0);
            FFMA2(pacc[0][1], b0, s1); FFMA2(pacc[1][1], b1, s1); FFMA2(pacc[2][1], b2, s1); FFMA2(pacc[3][1], b3, s1);
            FFMA2(pacc[0][2], b0, s2); FFMA2(pacc[1][2], b1, s2); FFMA2(pacc[2][2], b2, s2); FFMA2(pacc[3][2], b3, s2);
            FFMA2(pacc[0][3], b0, s3); FFMA2(pacc[1][3], b1, s3); FFMA2(pacc[2][3], b2, s3); FFMA2(pacc[3][3], b3, s3);
        }
        #pragma unroll 8
        for (int j = 0; j < NXDIM; j++) {
            float4 a = *(const float4*)(At + j * NXDIM + i0);
            ull a0, a1, a2, a3;
            PACKB(a0, a.x); PACKB(a1, a.y); PACKB(a2, a.z); PACKB(a3, a.w);
            int rs = j * RB + swz(j, r0);
            ulonglong2 sa = *(const ulonglong2*)(sshC + rs);
            ulonglong2 sb = *(const ulonglong2*)(sshC + (rs ^ 4));
            ull s0 = sa.x, s1 = sa.y, s2 = sb.x, s3 = sb.y;
            FFMA2(pacc[0][0], a0, s0); FFMA2(pacc[1][0], a1, s0); FFMA2(pacc[2][0], a2, s0); FFMA2(pacc[3][0], a3, s0);
            FFMA2(pacc[0][1], a0, s1); FFMA2(pacc[1][1], a1, s1); FFMA2(pacc[2][1], a2, s1); FFMA2(pacc[3][1], a3, s1);
            FFMA2(pacc[0][2], a0, s2); FFMA2(pacc[1][2], a1, s2); FFMA2(pacc[2][2], a2, s2); FFMA2(pacc[3][2], a3, s2);
            FFMA2(pacc[0][3], a0, s3); FFMA2(pacc[1][3], a1, s3); FFMA2(pacc[2][3], a2, s3); FFMA2(pacc[3][3], a3, s3);
        }

        #pragma unroll
        for (int ii = 0; ii < 4; ii++) {
            int i = i0 + ii;
            int rs = swz(i, r0);
            *(ulonglong2*)(sshN + i * RB + rs)       = make_ulonglong2(pacc[ii][0], pacc[ii][1]);
            *(ulonglong2*)(sshN + i * RB + (rs ^ 4)) = make_ulonglong2(pacc[ii][2], pacc[ii][3]);
        }
        __syncthreads();
    }
}

// ---------------------------------------------------------------------------
extern "C" void kernel_launch(void* const* d_in, const int* in_sizes, int n_in,
                              void* d_out, int out_size) {
    (void)in_sizes; (void)n_in; (void)out_size;
    const float* u   = (const float*)d_in[0];
    const float* A   = (const float*)d_in[1];
    const float* Bu  = (const float*)d_in[2];
    const float* Cy  = (const float*)d_in[3];
    const float* Dyu = (const float*)d_in[4];
    float* outY = (float*)d_out;
    float* outX = outY + (size_t)NSTEP * NYDIM * RB;

    const int smem_powers = (NXDIM * 65 + NXDIM * 128) * (int)sizeof(float);
    const int smem_fgemm  = (128 * NXDIM + 32 * 128) * (int)sizeof(float);
    const int smem_expand = (NXDIM * NXDIM + NUDIM * NXDIM + NXDIM * NYDIM +
                             2 * SSLOT + 2 * USLOT) * (int)sizeof(float);   // ~88 KB

    cudaFuncSetAttribute(k_powers, cudaFuncAttributeMaxDynamicSharedMemorySize, smem_powers);
    cudaFuncSetAttribute(k_fgemm,  cudaFuncAttributeMaxDynamicSharedMemorySize, smem_fgemm);
    cudaFuncSetAttribute(k_expand, cudaFuncAttributeMaxDynamicSharedMemorySize, smem_expand);

    k_powers<<<1, 1024, smem_powers>>>(A, Bu);
    k_fgemm<<<MBLK, 256, smem_fgemm>>>(u);
    k_scan<<<RB, 128>>>();
    k_expand<<<MBLK, 256, smem_expand>>>(u, A, Bu, Cy, Dyu, outY, outX);
}